// round 14
// baseline (speedup 1.0000x reference)
#include <cuda_runtime.h>
#include <cuda_bf16.h>
#include <cstdint>

#define BB 4
#define SS 1024
#define HH 1024
#define NHEADS 16
#define DKH 64

// Scratch: q-projection, k-projection, attention output (pre final GEMM)
__device__ float g_q[BB * SS * HH];
__device__ float g_k[BB * SS * HH];
__device__ float g_attn[BB * SS * HH];

// ===========================================================================
// Common MMA helpers (bf16 split precision)
// ===========================================================================
__device__ __forceinline__ uint32_t smem_u32(const void* p) {
    return (uint32_t)__cvta_generic_to_shared(p);
}
__device__ __forceinline__ void ldmat_x4(uint32_t* r, uint32_t addr) {
    asm volatile("ldmatrix.sync.aligned.m8n8.x4.shared.b16 {%0,%1,%2,%3}, [%4];"
        : "=r"(r[0]), "=r"(r[1]), "=r"(r[2]), "=r"(r[3]) : "r"(addr));
}
__device__ __forceinline__ void ldmat_x4_t(uint32_t* r, uint32_t addr) {
    asm volatile("ldmatrix.sync.aligned.m8n8.x4.trans.shared.b16 {%0,%1,%2,%3}, [%4];"
        : "=r"(r[0]), "=r"(r[1]), "=r"(r[2]), "=r"(r[3]) : "r"(addr));
}
__device__ __forceinline__ void mma_bf16(float (&d)[4], const uint32_t* a,
                                         uint32_t b0, uint32_t b1) {
    asm volatile("mma.sync.aligned.m16n8k16.row.col.f32.bf16.bf16.f32 "
        "{%0,%1,%2,%3}, {%4,%5,%6,%7}, {%8,%9}, {%0,%1,%2,%3};"
        : "+f"(d[0]), "+f"(d[1]), "+f"(d[2]), "+f"(d[3])
        : "r"(a[0]), "r"(a[1]), "r"(a[2]), "r"(a[3]), "r"(b0), "r"(b1));
}
__device__ __forceinline__ __nv_bfloat162 split_hi(float x0, float x1, __nv_bfloat162& lo) {
    __nv_bfloat16 h0 = __float2bfloat16(x0);
    __nv_bfloat16 h1 = __float2bfloat16(x1);
    lo.x = __float2bfloat16(x0 - __bfloat162float(h0));
    lo.y = __float2bfloat16(x1 - __bfloat162float(h1));
    __nv_bfloat162 hi; hi.x = h0; hi.y = h1;
    return hi;
}
__device__ __forceinline__ uint32_t bf2_u32(__nv_bfloat162 v) {
    return *(uint32_t*)&v;
}

// ===========================================================================
// bf16-split tensor-core GEMM (R8-proven):  C = A @ W + bias
// Tile 128x64x32, 256 thr, 8 warps (4x2), warp tile 32x32, static smem.
// ===========================================================================
#define GBM 128
#define GBN 64
#define GBK 32
#define ASTR (GBK + 8)
#define BSTR (GBN + 8)

__device__ __forceinline__ void gemm_body256(
    const float* __restrict__ A, const float* __restrict__ W,
    const float* __restrict__ bias, float* __restrict__ C,
    int M, int N, int K)
{
    __shared__ __nv_bfloat16 Ah[GBM][ASTR];
    __shared__ __nv_bfloat16 Al[GBM][ASTR];
    __shared__ __nv_bfloat16 Bh[GBK][BSTR];
    __shared__ __nv_bfloat16 Bl[GBK][BSTR];

    const int tid = threadIdx.x;
    const int wid = tid >> 5, lane = tid & 31;
    const int m0 = blockIdx.y * GBM, n0 = blockIdx.x * GBN;
    const int wm = (wid & 3) << 5;
    const int wn = (wid >> 2) << 5;

    float d[2][4][4];
    #pragma unroll
    for (int mf = 0; mf < 2; mf++)
        #pragma unroll
        for (int nf = 0; nf < 4; nf++)
            #pragma unroll
            for (int r = 0; r < 4; r++) d[mf][nf][r] = 0.f;

    const int ar = tid >> 3;
    const int ac = (tid & 7) << 2;
    const int br = tid >> 4;
    const int bc = (tid & 15) << 2;

    const float* Abase = A + (size_t)(m0 + ar) * K + ac;
    const float* Wbase = W + (size_t)br * N + n0 + bc;

    float4 av[4], bv[2];
    #pragma unroll
    for (int i = 0; i < 4; i++) av[i] = *(const float4*)(Abase + (size_t)(32 * i) * K);
    #pragma unroll
    for (int i = 0; i < 2; i++) bv[i] = *(const float4*)(Wbase + (size_t)(16 * i) * N);

    for (int k0 = 0; k0 < K; k0 += GBK) {
        __syncthreads();
        #pragma unroll
        for (int i = 0; i < 4; i++) {
            __nv_bfloat162 lo0, lo1;
            __nv_bfloat162 hi0 = split_hi(av[i].x, av[i].y, lo0);
            __nv_bfloat162 hi1 = split_hi(av[i].z, av[i].w, lo1);
            *(__nv_bfloat162*)&Ah[ar + 32 * i][ac]     = hi0;
            *(__nv_bfloat162*)&Ah[ar + 32 * i][ac + 2] = hi1;
            *(__nv_bfloat162*)&Al[ar + 32 * i][ac]     = lo0;
            *(__nv_bfloat162*)&Al[ar + 32 * i][ac + 2] = lo1;
        }
        #pragma unroll
        for (int i = 0; i < 2; i++) {
            __nv_bfloat162 lo0, lo1;
            __nv_bfloat162 hi0 = split_hi(bv[i].x, bv[i].y, lo0);
            __nv_bfloat162 hi1 = split_hi(bv[i].z, bv[i].w, lo1);
            *(__nv_bfloat162*)&Bh[br + 16 * i][bc]     = hi0;
            *(__nv_bfloat162*)&Bh[br + 16 * i][bc + 2] = hi1;
            *(__nv_bfloat162*)&Bl[br + 16 * i][bc]     = lo0;
            *(__nv_bfloat162*)&Bl[br + 16 * i][bc + 2] = lo1;
        }
        __syncthreads();

        int kn = k0 + GBK;
        if (kn < K) {
            #pragma unroll
            for (int i = 0; i < 4; i++)
                av[i] = *(const float4*)(Abase + (size_t)(32 * i) * K + kn);
            #pragma unroll
            for (int i = 0; i < 2; i++)
                bv[i] = *(const float4*)(Wbase + (size_t)(16 * i) * N + (size_t)kn * N);
        }

        #pragma unroll
        for (int kk = 0; kk < GBK; kk += 16) {
            uint32_t ahf[2][4], alf[2][4], bhf[2][4], blf[2][4];
            #pragma unroll
            for (int mf = 0; mf < 2; mf++) {
                int row = wm + mf * 16 + (lane & 15);
                int col = kk + ((lane >> 4) << 3);
                ldmat_x4(ahf[mf], smem_u32(&Ah[row][col]));
                ldmat_x4(alf[mf], smem_u32(&Al[row][col]));
            }
            #pragma unroll
            for (int nf2 = 0; nf2 < 2; nf2++) {
                int row = kk + (lane & 15);
                int col = wn + nf2 * 16 + ((lane >> 4) << 3);
                ldmat_x4_t(bhf[nf2], smem_u32(&Bh[row][col]));
                ldmat_x4_t(blf[nf2], smem_u32(&Bl[row][col]));
            }
            #pragma unroll
            for (int mf = 0; mf < 2; mf++)
                #pragma unroll
                for (int nf = 0; nf < 4; nf++) {
                    uint32_t bh0 = bhf[nf >> 1][(nf & 1) << 1];
                    uint32_t bh1 = bhf[nf >> 1][((nf & 1) << 1) + 1];
                    uint32_t bl0 = blf[nf >> 1][(nf & 1) << 1];
                    uint32_t bl1 = blf[nf >> 1][((nf & 1) << 1) + 1];
                    mma_bf16(d[mf][nf], ahf[mf], bh0, bh1);
                    mma_bf16(d[mf][nf], ahf[mf], bl0, bl1);
                    mma_bf16(d[mf][nf], alf[mf], bh0, bh1);
                }
        }
    }

    #pragma unroll
    for (int mf = 0; mf < 2; mf++) {
        int row = m0 + wm + mf * 16 + (lane >> 2);
        #pragma unroll
        for (int nf = 0; nf < 4; nf++) {
            int col = n0 + wn + nf * 8 + ((lane & 3) << 1);
            float2 bb = *(const float2*)&bias[col];
            float2 v0 = make_float2(d[mf][nf][0] + bb.x, d[mf][nf][1] + bb.y);
            float2 v1 = make_float2(d[mf][nf][2] + bb.x, d[mf][nf][3] + bb.y);
            *(float2*)&C[(size_t)row * N + col] = v0;
            *(float2*)&C[(size_t)(row + 8) * N + col] = v1;
        }
    }
}

__global__ __launch_bounds__(256) void gemm_mma_bias(
    const float* __restrict__ A, const float* __restrict__ W,
    const float* __restrict__ bias, float* __restrict__ C,
    int M, int N, int K)
{
    gemm_body256(A, W, bias, C, M, N, K);
}

// Merged Q+K projection: blockIdx.z selects the projection (wave packing).
__global__ __launch_bounds__(256) void gemm_qk_fused(
    const float* __restrict__ Aq, const float* __restrict__ Wq,
    const float* __restrict__ bq, float* __restrict__ Cq,
    const float* __restrict__ Ak, const float* __restrict__ Wk,
    const float* __restrict__ bk, float* __restrict__ Ck,
    int M, int N, int K)
{
    if (blockIdx.z == 0) gemm_body256(Aq, Wq, bq, Cq, M, N, K);
    else                 gemm_body256(Ak, Wk, bk, Ck, M, N, K);
}

// ===========================================================================
// FA2-style tensor-core attention (R8-proven), bf16-split (3-pass).
// Block: 128 q rows x (b,h). 8 warps x m16 slab. KV tile = 64.
// Only change vs R8: mask loads hoisted above the QK^T MMA loop.
// ===========================================================================
#define QT 128
#define KVT 64
#define QSTR 72

__global__ __launch_bounds__(256) void attn_mma_kernel(
    const float* __restrict__ qp, const float* __restrict__ kp,
    const int* __restrict__ mask, float* __restrict__ out)
{
    __shared__ __nv_bfloat16 sbuf[2 * 128 * QSTR];

    const int tid = threadIdx.x;
    const int wid = tid >> 5, lane = tid & 31;
    const int b = blockIdx.z, h = blockIdx.y;
    const int m0 = blockIdx.x * QT;
    const int warpM = wid << 4;

    {
        __nv_bfloat16* Qh = sbuf;
        __nv_bfloat16* Ql = sbuf + 128 * QSTR;
        int row = tid >> 1;
        int dbase = (tid & 1) << 5;
        const float* src = qp + (size_t)(b * SS + m0 + row) * HH + h * DKH + dbase;
        #pragma unroll
        for (int i = 0; i < 8; i++) {
            float4 v = *(const float4*)(src + 4 * i);
            __nv_bfloat162 lo0, lo1;
            __nv_bfloat162 hi0 = split_hi(v.x, v.y, lo0);
            __nv_bfloat162 hi1 = split_hi(v.z, v.w, lo1);
            *(__nv_bfloat162*)&Qh[row * QSTR + dbase + 4 * i]     = hi0;
            *(__nv_bfloat162*)&Qh[row * QSTR + dbase + 4 * i + 2] = hi1;
            *(__nv_bfloat162*)&Ql[row * QSTR + dbase + 4 * i]     = lo0;
            *(__nv_bfloat162*)&Ql[row * QSTR + dbase + 4 * i + 2] = lo1;
        }
    }
    __syncthreads();

    uint32_t qh[4][4], ql[4][4];
    {
        __nv_bfloat16* Qh = sbuf;
        __nv_bfloat16* Ql = sbuf + 128 * QSTR;
        #pragma unroll
        for (int kc = 0; kc < 4; kc++) {
            int row = warpM + (lane & 15);
            int col = (kc << 4) + ((lane >> 4) << 3);
            ldmat_x4(qh[kc], smem_u32(&Qh[row * QSTR + col]));
            ldmat_x4(ql[kc], smem_u32(&Ql[row * QSTR + col]));
        }
    }

    __nv_bfloat16* Kh = sbuf;
    __nv_bfloat16* Kl = sbuf + 64 * QSTR;
    __nv_bfloat16* Vh = sbuf + 2 * 64 * QSTR;
    __nv_bfloat16* Vl = sbuf + 3 * 64 * QSTR;

    float oacc[8][4];
    #pragma unroll
    for (int nf = 0; nf < 8; nf++)
        #pragma unroll
        for (int r = 0; r < 4; r++) oacc[nf][r] = 0.f;
    float mrun0 = -1e30f, mrun1 = -1e30f, lrun0 = 0.f, lrun1 = 0.f;

    const int fr = lane >> 2;
    const int cofs = (lane & 3) << 1;

    for (int n0 = 0; n0 < SS; n0 += KVT) {
        __syncthreads();
        {
            int row = tid >> 2;
            int dbase = (tid & 3) << 4;
            const float* ksrc = kp + (size_t)(b * SS + n0 + row) * HH + h * DKH + dbase;
            const float* vsrc = qp + (size_t)(b * SS + n0 + row) * HH + h * DKH + dbase;
            #pragma unroll
            for (int i = 0; i < 4; i++) {
                float4 v = *(const float4*)(ksrc + 4 * i);
                __nv_bfloat162 lo0, lo1;
                __nv_bfloat162 hi0 = split_hi(v.x, v.y, lo0);
                __nv_bfloat162 hi1 = split_hi(v.z, v.w, lo1);
                *(__nv_bfloat162*)&Kh[row * QSTR + dbase + 4 * i]     = hi0;
                *(__nv_bfloat162*)&Kh[row * QSTR + dbase + 4 * i + 2] = hi1;
                *(__nv_bfloat162*)&Kl[row * QSTR + dbase + 4 * i]     = lo0;
                *(__nv_bfloat162*)&Kl[row * QSTR + dbase + 4 * i + 2] = lo1;
                v = *(const float4*)(vsrc + 4 * i);
                hi0 = split_hi(v.x, v.y, lo0);
                hi1 = split_hi(v.z, v.w, lo1);
                *(__nv_bfloat162*)&Vh[row * QSTR + dbase + 4 * i]     = hi0;
                *(__nv_bfloat162*)&Vh[row * QSTR + dbase + 4 * i + 2] = hi1;
                *(__nv_bfloat162*)&Vl[row * QSTR + dbase + 4 * i]     = lo0;
                *(__nv_bfloat162*)&Vl[row * QSTR + dbase + 4 * i + 2] = lo1;
            }
        }
        __syncthreads();

        // hoisted mask loads: latency hides under the 96 QK MMAs below
        int2 mv0[8], mv1[8];
        {
            const int* mp0 = mask + (size_t)(b * SS + m0 + warpM + fr) * SS + n0 + cofs;
            const int* mp1 = mp0 + (size_t)8 * SS;
            #pragma unroll
            for (int nf = 0; nf < 8; nf++) {
                mv0[nf] = *(const int2*)(mp0 + nf * 8);
                mv1[nf] = *(const int2*)(mp1 + nf * 8);
            }
        }

        float sacc[8][4];
        #pragma unroll
        for (int nf = 0; nf < 8; nf++)
            #pragma unroll
            for (int r = 0; r < 4; r++) sacc[nf][r] = 0.f;

        #pragma unroll
        for (int kc = 0; kc < 4; kc++) {
            #pragma unroll
            for (int t = 0; t < 4; t++) {
                uint32_t kh[4], kl[4];
                int row = (t << 4) + (lane & 15);
                int col = (kc << 4) + ((lane >> 4) << 3);
                ldmat_x4(kh, smem_u32(&Kh[row * QSTR + col]));
                ldmat_x4(kl, smem_u32(&Kl[row * QSTR + col]));
                mma_bf16(sacc[2 * t], qh[kc], kh[0], kh[2]);
                mma_bf16(sacc[2 * t], qh[kc], kl[0], kl[2]);
                mma_bf16(sacc[2 * t], ql[kc], kh[0], kh[2]);
                mma_bf16(sacc[2 * t + 1], qh[kc], kh[1], kh[3]);
                mma_bf16(sacc[2 * t + 1], qh[kc], kl[1], kl[3]);
                mma_bf16(sacc[2 * t + 1], ql[kc], kh[1], kh[3]);
            }
        }

        float mloc0 = -3e38f, mloc1 = -3e38f;
        #pragma unroll
        for (int nf = 0; nf < 8; nf++) {
            sacc[nf][0] = mv0[nf].x ? -1e9f : sacc[nf][0] * 0.125f;
            sacc[nf][1] = mv0[nf].y ? -1e9f : sacc[nf][1] * 0.125f;
            sacc[nf][2] = mv1[nf].x ? -1e9f : sacc[nf][2] * 0.125f;
            sacc[nf][3] = mv1[nf].y ? -1e9f : sacc[nf][3] * 0.125f;
            mloc0 = fmaxf(mloc0, fmaxf(sacc[nf][0], sacc[nf][1]));
            mloc1 = fmaxf(mloc1, fmaxf(sacc[nf][2], sacc[nf][3]));
        }
        mloc0 = fmaxf(mloc0, __shfl_xor_sync(0xffffffffu, mloc0, 1));
        mloc0 = fmaxf(mloc0, __shfl_xor_sync(0xffffffffu, mloc0, 2));
        mloc1 = fmaxf(mloc1, __shfl_xor_sync(0xffffffffu, mloc1, 1));
        mloc1 = fmaxf(mloc1, __shfl_xor_sync(0xffffffffu, mloc1, 2));

        float mnew0 = fmaxf(mrun0, mloc0), mnew1 = fmaxf(mrun1, mloc1);
        float corr0 = __expf(mrun0 - mnew0), corr1 = __expf(mrun1 - mnew1);
        mrun0 = mnew0; mrun1 = mnew1;

        float ls0 = 0.f, ls1 = 0.f;
        #pragma unroll
        for (int nf = 0; nf < 8; nf++) {
            sacc[nf][0] = __expf(sacc[nf][0] - mnew0);
            sacc[nf][1] = __expf(sacc[nf][1] - mnew0);
            sacc[nf][2] = __expf(sacc[nf][2] - mnew1);
            sacc[nf][3] = __expf(sacc[nf][3] - mnew1);
            ls0 += sacc[nf][0] + sacc[nf][1];
            ls1 += sacc[nf][2] + sacc[nf][3];
        }
        ls0 += __shfl_xor_sync(0xffffffffu, ls0, 1);
        ls0 += __shfl_xor_sync(0xffffffffu, ls0, 2);
        ls1 += __shfl_xor_sync(0xffffffffu, ls1, 1);
        ls1 += __shfl_xor_sync(0xffffffffu, ls1, 2);
        lrun0 = lrun0 * corr0 + ls0;
        lrun1 = lrun1 * corr1 + ls1;

        #pragma unroll
        for (int nf = 0; nf < 8; nf++) {
            oacc[nf][0] *= corr0; oacc[nf][1] *= corr0;
            oacc[nf][2] *= corr1; oacc[nf][3] *= corr1;
        }

        uint32_t pha[8], phb[8], pla[8], plb[8];
        #pragma unroll
        for (int nf = 0; nf < 8; nf++) {
            __nv_bfloat162 lo;
            __nv_bfloat162 hi = split_hi(sacc[nf][0], sacc[nf][1], lo);
            pha[nf] = bf2_u32(hi); pla[nf] = bf2_u32(lo);
            hi = split_hi(sacc[nf][2], sacc[nf][3], lo);
            phb[nf] = bf2_u32(hi); plb[nf] = bf2_u32(lo);
        }

        #pragma unroll
        for (int j = 0; j < 4; j++) {
            uint32_t ah[4] = {pha[2 * j], phb[2 * j], pha[2 * j + 1], phb[2 * j + 1]};
            uint32_t al[4] = {pla[2 * j], plb[2 * j], pla[2 * j + 1], plb[2 * j + 1]};
            #pragma unroll
            for (int t = 0; t < 4; t++) {
                uint32_t vh[4], vl[4];
                int row = (j << 4) + (lane & 15);
                int col = (t << 4) + ((lane >> 4) << 3);
                ldmat_x4_t(vh, smem_u32(&Vh[row * QSTR + col]));
                ldmat_x4_t(vl, smem_u32(&Vl[row * QSTR + col]));
                mma_bf16(oacc[2 * t], ah, vh[0], vh[1]);
                mma_bf16(oacc[2 * t], ah, vl[0], vl[1]);
                mma_bf16(oacc[2 * t], al, vh[0], vh[1]);
                mma_bf16(oacc[2 * t + 1], ah, vh[2], vh[3]);
                mma_bf16(oacc[2 * t + 1], ah, vl[2], vl[3]);
                mma_bf16(oacc[2 * t + 1], al, vh[2], vh[3]);
            }
        }
    }

    {
        int grow0 = m0 + warpM + fr;
        float keep0 = mask[(size_t)(b * SS + grow0) * SS] ? 0.f : 1.f;
        float keep1 = mask[(size_t)(b * SS + grow0 + 8) * SS] ? 0.f : 1.f;
        float inv0 = keep0 / lrun0;
        float inv1 = keep1 / lrun1;
        float* o0 = out + (size_t)(b * SS + grow0) * HH + h * DKH + cofs;
        float* o1 = o0 + (size_t)8 * HH;
        #pragma unroll
        for (int nf = 0; nf < 8; nf++) {
            *(float2*)(o0 + nf * 8) = make_float2(oacc[nf][0] * inv0, oacc[nf][1] * inv0);
            *(float2*)(o1 + nf * 8) = make_float2(oacc[nf][2] * inv1, oacc[nf][3] * inv1);
        }
    }
}

// ---------------------------------------------------------------------------
extern "C" void kernel_launch(void* const* d_in, const int* in_sizes, int n_in,
                              void* d_out, int out_size)
{
    const float* query  = (const float*)d_in[0];
    const float* key_in = (const float*)d_in[1];
    const int*   mask   = (const int*)d_in[2];
    const float* Wq     = (const float*)d_in[3];
    const float* bq     = (const float*)d_in[4];
    const float* Wk     = (const float*)d_in[5];
    const float* bk     = (const float*)d_in[6];
    const float* Wp     = (const float*)d_in[7];
    const float* bp     = (const float*)d_in[8];
    float* out = (float*)d_out;

    float *qp, *kp, *ap;
    cudaGetSymbolAddress((void**)&qp, g_q);
    cudaGetSymbolAddress((void**)&kp, g_k);
    cudaGetSymbolAddress((void**)&ap, g_attn);

    const int M = BB * SS, N = HH, K = HH;

    dim3 qkgrid(N / GBN, M / GBM, 2);   // (16, 32, 2)
    gemm_qk_fused<<<qkgrid, 256>>>(query, Wq, bq, qp, key_in, Wk, bk, kp, M, N, K);

    attn_mma_kernel<<<dim3(SS / QT, NHEADS, BB), 256>>>(qp, kp, mask, ap);

    dim3 ggrid(N / GBN, M / GBM);       // (16, 32)
    gemm_mma_bias<<<ggrid, 256>>>(ap, Wp, bp, out, M, N, K);
}

// round 16
// speedup vs baseline: 1.1007x; 1.1007x over previous
#include <cuda_runtime.h>
#include <cuda_bf16.h>
#include <cstdint>

#define BB 4
#define SS 1024
#define HH 1024
#define NHEADS 16
#define DKH 64

// Scratch: q-projection, k-projection, attention output (pre final GEMM)
__device__ float g_q[BB * SS * HH];
__device__ float g_k[BB * SS * HH];
__device__ float g_attn[BB * SS * HH];

// ===========================================================================
// Common MMA helpers (bf16 split precision)
// ===========================================================================
__device__ __forceinline__ uint32_t smem_u32(const void* p) {
    return (uint32_t)__cvta_generic_to_shared(p);
}
__device__ __forceinline__ void ldmat_x4(uint32_t* r, uint32_t addr) {
    asm volatile("ldmatrix.sync.aligned.m8n8.x4.shared.b16 {%0,%1,%2,%3}, [%4];"
        : "=r"(r[0]), "=r"(r[1]), "=r"(r[2]), "=r"(r[3]) : "r"(addr));
}
__device__ __forceinline__ void ldmat_x4_t(uint32_t* r, uint32_t addr) {
    asm volatile("ldmatrix.sync.aligned.m8n8.x4.trans.shared.b16 {%0,%1,%2,%3}, [%4];"
        : "=r"(r[0]), "=r"(r[1]), "=r"(r[2]), "=r"(r[3]) : "r"(addr));
}
__device__ __forceinline__ void mma_bf16(float (&d)[4], const uint32_t* a,
                                         uint32_t b0, uint32_t b1) {
    asm volatile("mma.sync.aligned.m16n8k16.row.col.f32.bf16.bf16.f32 "
        "{%0,%1,%2,%3}, {%4,%5,%6,%7}, {%8,%9}, {%0,%1,%2,%3};"
        : "+f"(d[0]), "+f"(d[1]), "+f"(d[2]), "+f"(d[3])
        : "r"(a[0]), "r"(a[1]), "r"(a[2]), "r"(a[3]), "r"(b0), "r"(b1));
}
__device__ __forceinline__ __nv_bfloat162 split_hi(float x0, float x1, __nv_bfloat162& lo) {
    __nv_bfloat16 h0 = __float2bfloat16(x0);
    __nv_bfloat16 h1 = __float2bfloat16(x1);
    lo.x = __float2bfloat16(x0 - __bfloat162float(h0));
    lo.y = __float2bfloat16(x1 - __bfloat162float(h1));
    __nv_bfloat162 hi; hi.x = h0; hi.y = h1;
    return hi;
}
__device__ __forceinline__ uint32_t bf2_u32(__nv_bfloat162 v) {
    return *(uint32_t*)&v;
}

// ===========================================================================
// bf16-split tensor-core GEMM (R8-proven):  C = A @ W + bias
// Tile 128x64x32, 256 thr, 8 warps (4x2), warp tile 32x32, static smem.
// ===========================================================================
#define GBM 128
#define GBN 64
#define GBK 32
#define ASTR (GBK + 8)
#define BSTR (GBN + 8)

__device__ __forceinline__ void gemm_body256(
    const float* __restrict__ A, const float* __restrict__ W,
    const float* __restrict__ bias, float* __restrict__ C,
    int M, int N, int K)
{
    __shared__ __nv_bfloat16 Ah[GBM][ASTR];
    __shared__ __nv_bfloat16 Al[GBM][ASTR];
    __shared__ __nv_bfloat16 Bh[GBK][BSTR];
    __shared__ __nv_bfloat16 Bl[GBK][BSTR];

    const int tid = threadIdx.x;
    const int wid = tid >> 5, lane = tid & 31;
    const int m0 = blockIdx.y * GBM, n0 = blockIdx.x * GBN;
    const int wm = (wid & 3) << 5;
    const int wn = (wid >> 2) << 5;

    float d[2][4][4];
    #pragma unroll
    for (int mf = 0; mf < 2; mf++)
        #pragma unroll
        for (int nf = 0; nf < 4; nf++)
            #pragma unroll
            for (int r = 0; r < 4; r++) d[mf][nf][r] = 0.f;

    const int ar = tid >> 3;
    const int ac = (tid & 7) << 2;
    const int br = tid >> 4;
    const int bc = (tid & 15) << 2;

    const float* Abase = A + (size_t)(m0 + ar) * K + ac;
    const float* Wbase = W + (size_t)br * N + n0 + bc;

    float4 av[4], bv[2];
    #pragma unroll
    for (int i = 0; i < 4; i++) av[i] = *(const float4*)(Abase + (size_t)(32 * i) * K);
    #pragma unroll
    for (int i = 0; i < 2; i++) bv[i] = *(const float4*)(Wbase + (size_t)(16 * i) * N);

    for (int k0 = 0; k0 < K; k0 += GBK) {
        __syncthreads();
        #pragma unroll
        for (int i = 0; i < 4; i++) {
            __nv_bfloat162 lo0, lo1;
            __nv_bfloat162 hi0 = split_hi(av[i].x, av[i].y, lo0);
            __nv_bfloat162 hi1 = split_hi(av[i].z, av[i].w, lo1);
            *(__nv_bfloat162*)&Ah[ar + 32 * i][ac]     = hi0;
            *(__nv_bfloat162*)&Ah[ar + 32 * i][ac + 2] = hi1;
            *(__nv_bfloat162*)&Al[ar + 32 * i][ac]     = lo0;
            *(__nv_bfloat162*)&Al[ar + 32 * i][ac + 2] = lo1;
        }
        #pragma unroll
        for (int i = 0; i < 2; i++) {
            __nv_bfloat162 lo0, lo1;
            __nv_bfloat162 hi0 = split_hi(bv[i].x, bv[i].y, lo0);
            __nv_bfloat162 hi1 = split_hi(bv[i].z, bv[i].w, lo1);
            *(__nv_bfloat162*)&Bh[br + 16 * i][bc]     = hi0;
            *(__nv_bfloat162*)&Bh[br + 16 * i][bc + 2] = hi1;
            *(__nv_bfloat162*)&Bl[br + 16 * i][bc]     = lo0;
            *(__nv_bfloat162*)&Bl[br + 16 * i][bc + 2] = lo1;
        }
        __syncthreads();

        int kn = k0 + GBK;
        if (kn < K) {
            #pragma unroll
            for (int i = 0; i < 4; i++)
                av[i] = *(const float4*)(Abase + (size_t)(32 * i) * K + kn);
            #pragma unroll
            for (int i = 0; i < 2; i++)
                bv[i] = *(const float4*)(Wbase + (size_t)(16 * i) * N + (size_t)kn * N);
        }

        #pragma unroll
        for (int kk = 0; kk < GBK; kk += 16) {
            uint32_t ahf[2][4], alf[2][4], bhf[2][4], blf[2][4];
            #pragma unroll
            for (int mf = 0; mf < 2; mf++) {
                int row = wm + mf * 16 + (lane & 15);
                int col = kk + ((lane >> 4) << 3);
                ldmat_x4(ahf[mf], smem_u32(&Ah[row][col]));
                ldmat_x4(alf[mf], smem_u32(&Al[row][col]));
            }
            #pragma unroll
            for (int nf2 = 0; nf2 < 2; nf2++) {
                int row = kk + (lane & 15);
                int col = wn + nf2 * 16 + ((lane >> 4) << 3);
                ldmat_x4_t(bhf[nf2], smem_u32(&Bh[row][col]));
                ldmat_x4_t(blf[nf2], smem_u32(&Bl[row][col]));
            }
            #pragma unroll
            for (int mf = 0; mf < 2; mf++)
                #pragma unroll
                for (int nf = 0; nf < 4; nf++) {
                    uint32_t bh0 = bhf[nf >> 1][(nf & 1) << 1];
                    uint32_t bh1 = bhf[nf >> 1][((nf & 1) << 1) + 1];
                    uint32_t bl0 = blf[nf >> 1][(nf & 1) << 1];
                    uint32_t bl1 = blf[nf >> 1][((nf & 1) << 1) + 1];
                    mma_bf16(d[mf][nf], ahf[mf], bh0, bh1);
                    mma_bf16(d[mf][nf], ahf[mf], bl0, bl1);
                    mma_bf16(d[mf][nf], alf[mf], bh0, bh1);
                }
        }
    }

    #pragma unroll
    for (int mf = 0; mf < 2; mf++) {
        int row = m0 + wm + mf * 16 + (lane >> 2);
        #pragma unroll
        for (int nf = 0; nf < 4; nf++) {
            int col = n0 + wn + nf * 8 + ((lane & 3) << 1);
            float2 bb = *(const float2*)&bias[col];
            float2 v0 = make_float2(d[mf][nf][0] + bb.x, d[mf][nf][1] + bb.y);
            float2 v1 = make_float2(d[mf][nf][2] + bb.x, d[mf][nf][3] + bb.y);
            *(float2*)&C[(size_t)row * N + col] = v0;
            *(float2*)&C[(size_t)(row + 8) * N + col] = v1;
        }
    }
}

__global__ __launch_bounds__(256) void gemm_mma_bias(
    const float* __restrict__ A, const float* __restrict__ W,
    const float* __restrict__ bias, float* __restrict__ C,
    int M, int N, int K)
{
    gemm_body256(A, W, bias, C, M, N, K);
}

// Merged Q+K projection: blockIdx.z selects the projection (wave packing).
__global__ __launch_bounds__(256) void gemm_qk_fused(
    const float* __restrict__ Aq, const float* __restrict__ Wq,
    const float* __restrict__ bq, float* __restrict__ Cq,
    const float* __restrict__ Ak, const float* __restrict__ Wk,
    const float* __restrict__ bk, float* __restrict__ Ck,
    int M, int N, int K)
{
    if (blockIdx.z == 0) gemm_body256(Aq, Wq, bq, Cq, M, N, K);
    else                 gemm_body256(Ak, Wk, bk, Ck, M, N, K);
}

// ===========================================================================
// FA2-style tensor-core attention, bf16-split (3-pass) for QK^T and PV.
// Block: 128 q rows x (b,h). 8 warps, each an m16 slab. KV tile = 64.
// EXACT R8 version (measured ~230us; mask loads inline).
// ===========================================================================
#define QT 128
#define KVT 64
#define QSTR 72

__global__ __launch_bounds__(256) void attn_mma_kernel(
    const float* __restrict__ qp, const float* __restrict__ kp,
    const int* __restrict__ mask, float* __restrict__ out)
{
    __shared__ __nv_bfloat16 sbuf[2 * 128 * QSTR];

    const int tid = threadIdx.x;
    const int wid = tid >> 5, lane = tid & 31;
    const int b = blockIdx.z, h = blockIdx.y;
    const int m0 = blockIdx.x * QT;
    const int warpM = wid << 4;

    {
        __nv_bfloat16* Qh = sbuf;
        __nv_bfloat16* Ql = sbuf + 128 * QSTR;
        int row = tid >> 1;
        int dbase = (tid & 1) << 5;
        const float* src = qp + (size_t)(b * SS + m0 + row) * HH + h * DKH + dbase;
        #pragma unroll
        for (int i = 0; i < 8; i++) {
            float4 v = *(const float4*)(src + 4 * i);
            __nv_bfloat162 lo0, lo1;
            __nv_bfloat162 hi0 = split_hi(v.x, v.y, lo0);
            __nv_bfloat162 hi1 = split_hi(v.z, v.w, lo1);
            *(__nv_bfloat162*)&Qh[row * QSTR + dbase + 4 * i]     = hi0;
            *(__nv_bfloat162*)&Qh[row * QSTR + dbase + 4 * i + 2] = hi1;
            *(__nv_bfloat162*)&Ql[row * QSTR + dbase + 4 * i]     = lo0;
            *(__nv_bfloat162*)&Ql[row * QSTR + dbase + 4 * i + 2] = lo1;
        }
    }
    __syncthreads();

    uint32_t qh[4][4], ql[4][4];
    {
        __nv_bfloat16* Qh = sbuf;
        __nv_bfloat16* Ql = sbuf + 128 * QSTR;
        #pragma unroll
        for (int kc = 0; kc < 4; kc++) {
            int row = warpM + (lane & 15);
            int col = (kc << 4) + ((lane >> 4) << 3);
            ldmat_x4(qh[kc], smem_u32(&Qh[row * QSTR + col]));
            ldmat_x4(ql[kc], smem_u32(&Ql[row * QSTR + col]));
        }
    }

    __nv_bfloat16* Kh = sbuf;
    __nv_bfloat16* Kl = sbuf + 64 * QSTR;
    __nv_bfloat16* Vh = sbuf + 2 * 64 * QSTR;
    __nv_bfloat16* Vl = sbuf + 3 * 64 * QSTR;

    float oacc[8][4];
    #pragma unroll
    for (int nf = 0; nf < 8; nf++)
        #pragma unroll
        for (int r = 0; r < 4; r++) oacc[nf][r] = 0.f;
    float mrun0 = -1e30f, mrun1 = -1e30f, lrun0 = 0.f, lrun1 = 0.f;

    const int fr = lane >> 2;
    const int cofs = (lane & 3) << 1;

    for (int n0 = 0; n0 < SS; n0 += KVT) {
        __syncthreads();
        {
            int row = tid >> 2;
            int dbase = (tid & 3) << 4;
            const float* ksrc = kp + (size_t)(b * SS + n0 + row) * HH + h * DKH + dbase;
            const float* vsrc = qp + (size_t)(b * SS + n0 + row) * HH + h * DKH + dbase;
            #pragma unroll
            for (int i = 0; i < 4; i++) {
                float4 v = *(const float4*)(ksrc + 4 * i);
                __nv_bfloat162 lo0, lo1;
                __nv_bfloat162 hi0 = split_hi(v.x, v.y, lo0);
                __nv_bfloat162 hi1 = split_hi(v.z, v.w, lo1);
                *(__nv_bfloat162*)&Kh[row * QSTR + dbase + 4 * i]     = hi0;
                *(__nv_bfloat162*)&Kh[row * QSTR + dbase + 4 * i + 2] = hi1;
                *(__nv_bfloat162*)&Kl[row * QSTR + dbase + 4 * i]     = lo0;
                *(__nv_bfloat162*)&Kl[row * QSTR + dbase + 4 * i + 2] = lo1;
                v = *(const float4*)(vsrc + 4 * i);
                hi0 = split_hi(v.x, v.y, lo0);
                hi1 = split_hi(v.z, v.w, lo1);
                *(__nv_bfloat162*)&Vh[row * QSTR + dbase + 4 * i]     = hi0;
                *(__nv_bfloat162*)&Vh[row * QSTR + dbase + 4 * i + 2] = hi1;
                *(__nv_bfloat162*)&Vl[row * QSTR + dbase + 4 * i]     = lo0;
                *(__nv_bfloat162*)&Vl[row * QSTR + dbase + 4 * i + 2] = lo1;
            }
        }
        __syncthreads();

        float sacc[8][4];
        #pragma unroll
        for (int nf = 0; nf < 8; nf++)
            #pragma unroll
            for (int r = 0; r < 4; r++) sacc[nf][r] = 0.f;

        #pragma unroll
        for (int kc = 0; kc < 4; kc++) {
            #pragma unroll
            for (int t = 0; t < 4; t++) {
                uint32_t kh[4], kl[4];
                int row = (t << 4) + (lane & 15);
                int col = (kc << 4) + ((lane >> 4) << 3);
                ldmat_x4(kh, smem_u32(&Kh[row * QSTR + col]));
                ldmat_x4(kl, smem_u32(&Kl[row * QSTR + col]));
                mma_bf16(sacc[2 * t], qh[kc], kh[0], kh[2]);
                mma_bf16(sacc[2 * t], qh[kc], kl[0], kl[2]);
                mma_bf16(sacc[2 * t], ql[kc], kh[0], kh[2]);
                mma_bf16(sacc[2 * t + 1], qh[kc], kh[1], kh[3]);
                mma_bf16(sacc[2 * t + 1], qh[kc], kl[1], kl[3]);
                mma_bf16(sacc[2 * t + 1], ql[kc], kh[1], kh[3]);
            }
        }

        const int* mp0 = mask + (size_t)(b * SS + m0 + warpM + fr) * SS + n0 + cofs;
        const int* mp1 = mp0 + (size_t)8 * SS;
        float mloc0 = -3e38f, mloc1 = -3e38f;
        #pragma unroll
        for (int nf = 0; nf < 8; nf++) {
            int2 mv0 = *(const int2*)(mp0 + nf * 8);
            int2 mv1 = *(const int2*)(mp1 + nf * 8);
            sacc[nf][0] = mv0.x ? -1e9f : sacc[nf][0] * 0.125f;
            sacc[nf][1] = mv0.y ? -1e9f : sacc[nf][1] * 0.125f;
            sacc[nf][2] = mv1.x ? -1e9f : sacc[nf][2] * 0.125f;
            sacc[nf][3] = mv1.y ? -1e9f : sacc[nf][3] * 0.125f;
            mloc0 = fmaxf(mloc0, fmaxf(sacc[nf][0], sacc[nf][1]));
            mloc1 = fmaxf(mloc1, fmaxf(sacc[nf][2], sacc[nf][3]));
        }
        mloc0 = fmaxf(mloc0, __shfl_xor_sync(0xffffffffu, mloc0, 1));
        mloc0 = fmaxf(mloc0, __shfl_xor_sync(0xffffffffu, mloc0, 2));
        mloc1 = fmaxf(mloc1, __shfl_xor_sync(0xffffffffu, mloc1, 1));
        mloc1 = fmaxf(mloc1, __shfl_xor_sync(0xffffffffu, mloc1, 2));

        float mnew0 = fmaxf(mrun0, mloc0), mnew1 = fmaxf(mrun1, mloc1);
        float corr0 = __expf(mrun0 - mnew0), corr1 = __expf(mrun1 - mnew1);
        mrun0 = mnew0; mrun1 = mnew1;

        float ls0 = 0.f, ls1 = 0.f;
        #pragma unroll
        for (int nf = 0; nf < 8; nf++) {
            sacc[nf][0] = __expf(sacc[nf][0] - mnew0);
            sacc[nf][1] = __expf(sacc[nf][1] - mnew0);
            sacc[nf][2] = __expf(sacc[nf][2] - mnew1);
            sacc[nf][3] = __expf(sacc[nf][3] - mnew1);
            ls0 += sacc[nf][0] + sacc[nf][1];
            ls1 += sacc[nf][2] + sacc[nf][3];
        }
        ls0 += __shfl_xor_sync(0xffffffffu, ls0, 1);
        ls0 += __shfl_xor_sync(0xffffffffu, ls0, 2);
        ls1 += __shfl_xor_sync(0xffffffffu, ls1, 1);
        ls1 += __shfl_xor_sync(0xffffffffu, ls1, 2);
        lrun0 = lrun0 * corr0 + ls0;
        lrun1 = lrun1 * corr1 + ls1;

        #pragma unroll
        for (int nf = 0; nf < 8; nf++) {
            oacc[nf][0] *= corr0; oacc[nf][1] *= corr0;
            oacc[nf][2] *= corr1; oacc[nf][3] *= corr1;
        }

        uint32_t pha[8], phb[8], pla[8], plb[8];
        #pragma unroll
        for (int nf = 0; nf < 8; nf++) {
            __nv_bfloat162 lo;
            __nv_bfloat162 hi = split_hi(sacc[nf][0], sacc[nf][1], lo);
            pha[nf] = bf2_u32(hi); pla[nf] = bf2_u32(lo);
            hi = split_hi(sacc[nf][2], sacc[nf][3], lo);
            phb[nf] = bf2_u32(hi); plb[nf] = bf2_u32(lo);
        }

        #pragma unroll
        for (int j = 0; j < 4; j++) {
            uint32_t ah[4] = {pha[2 * j], phb[2 * j], pha[2 * j + 1], phb[2 * j + 1]};
            uint32_t al[4] = {pla[2 * j], plb[2 * j], pla[2 * j + 1], plb[2 * j + 1]};
            #pragma unroll
            for (int t = 0; t < 4; t++) {
                uint32_t vh[4], vl[4];
                int row = (j << 4) + (lane & 15);
                int col = (t << 4) + ((lane >> 4) << 3);
                ldmat_x4_t(vh, smem_u32(&Vh[row * QSTR + col]));
                ldmat_x4_t(vl, smem_u32(&Vl[row * QSTR + col]));
                mma_bf16(oacc[2 * t], ah, vh[0], vh[1]);
                mma_bf16(oacc[2 * t], ah, vl[0], vl[1]);
                mma_bf16(oacc[2 * t], al, vh[0], vh[1]);
                mma_bf16(oacc[2 * t + 1], ah, vh[2], vh[3]);
                mma_bf16(oacc[2 * t + 1], ah, vl[2], vl[3]);
                mma_bf16(oacc[2 * t + 1], al, vh[2], vh[3]);
            }
        }
    }

    {
        int grow0 = m0 + warpM + fr;
        float keep0 = mask[(size_t)(b * SS + grow0) * SS] ? 0.f : 1.f;
        float keep1 = mask[(size_t)(b * SS + grow0 + 8) * SS] ? 0.f : 1.f;
        float inv0 = keep0 / lrun0;
        float inv1 = keep1 / lrun1;
        float* o0 = out + (size_t)(b * SS + grow0) * HH + h * DKH + cofs;
        float* o1 = o0 + (size_t)8 * HH;
        #pragma unroll
        for (int nf = 0; nf < 8; nf++) {
            *(float2*)(o0 + nf * 8) = make_float2(oacc[nf][0] * inv0, oacc[nf][1] * inv0);
            *(float2*)(o1 + nf * 8) = make_float2(oacc[nf][2] * inv1, oacc[nf][3] * inv1);
        }
    }
}

// ---------------------------------------------------------------------------
extern "C" void kernel_launch(void* const* d_in, const int* in_sizes, int n_in,
                              void* d_out, int out_size)
{
    const float* query  = (const float*)d_in[0];
    const float* key_in = (const float*)d_in[1];
    const int*   mask   = (const int*)d_in[2];
    const float* Wq     = (const float*)d_in[3];
    const float* bq     = (const float*)d_in[4];
    const float* Wk     = (const float*)d_in[5];
    const float* bk     = (const float*)d_in[6];
    const float* Wp     = (const float*)d_in[7];
    const float* bp     = (const float*)d_in[8];
    float* out = (float*)d_out;

    float *qp, *kp, *ap;
    cudaGetSymbolAddress((void**)&qp, g_q);
    cudaGetSymbolAddress((void**)&kp, g_k);
    cudaGetSymbolAddress((void**)&ap, g_attn);

    const int M = BB * SS, N = HH, K = HH;

    dim3 qkgrid(N / GBN, M / GBM, 2);   // (16, 32, 2)
    gemm_qk_fused<<<qkgrid, 256>>>(query, Wq, bq, qp, key_in, Wk, bk, kp, M, N, K);

    attn_mma_kernel<<<dim3(SS / QT, NHEADS, BB), 256>>>(qp, kp, mask, ap);

    dim3 ggrid(N / GBN, M / GBM);       // (16, 32)
    gemm_mma_bias<<<ggrid, 256>>>(ap, Wp, bp, out, M, N, K);
}